// round 4
// baseline (speedup 1.0000x reference)
#include <cuda_runtime.h>
#include <cuda_bf16.h>
#include <math.h>

#define N_NODES 100000
#define E_EDGES 3200000
#define F_IN    500
#define HID     64
#define CCH     64
#define KFREQ   5
#define DORD    10

// ---------------- scratch (static device globals; no allocation) ----------------
__device__ __align__(16) float g_xh[N_NODES * HID];   // relu(feature@W1+b1)
__device__ __align__(16) float g_xc[N_NODES * CCH];   // lin2 output ("x" added at end)
__device__ __align__(16) float g_bufA[N_NODES * CCH];
__device__ __align__(16) float g_bufB[N_NODES * CCH];
__device__ __align__(16) float g_hidden[N_NODES * CCH];
__device__ __align__(16) long long g_colw[E_EDGES];   // packed {w(float hi32), src(lo32)}
__device__ int       g_deg[N_NODES];
__device__ int       g_indeg[N_NODES];
__device__ float     g_dinv[N_NODES];
__device__ int       g_rowptr[N_NODES + 1];
__device__ int       g_cursor[N_NODES + 1];
__device__ int       g_tmp[N_NODES];
__device__ int       g_btot[128];
__device__ int       g_boff[128];
__device__ float     g_coeff[16];

// ---------------- small utility kernels ----------------
__global__ void zero_counts_kernel() {
    int i = blockIdx.x * blockDim.x + threadIdx.x;
    if (i < N_NODES) { g_deg[i] = 0; g_indeg[i] = 0; }
}

// coeff[d] = sum_k alpha[k]*SINC[k][d] + beta[k]*COSC[k][d]
// tables computed in double precision then cast (matches reference).
__global__ void coeff_kernel(const float* __restrict__ alpha,
                             const float* __restrict__ beta) {
    int d = threadIdx.x;
    if (d > DORD) return;
    float acc = 0.0f;
    for (int k = 0; k < KFREQ; ++k) {
        double x = (double)(k + 1) * 3.14159265358979323846;
        double p = 1.0;
        for (int i = 0; i < d; ++i) p *= x;
        double f = 1.0;
        for (int i = 2; i <= d; ++i) f *= (double)i;
        double sinc = 0.0, cosc = 0.0;
        if ((d & 1) == 0) {
            double sgn = (((d / 2) & 1) == 0) ? 1.0 : -1.0;
            cosc = sgn * p / f;
        } else {
            double sgn = ((((d - 1) / 2) & 1) == 0) ? 1.0 : -1.0;
            sinc = sgn * p / f;
        }
        acc += alpha[k] * (float)sinc + beta[k] * (float)cosc;
    }
    g_coeff[d] = acc;
}

// degree (out-deg over non-self-loop edges, keyed by src) + in-degree (for CSR)
// NOTE: edges buffer is int32 (jax default x64-disabled downcasts int64->int32)
__global__ void pass1_kernel(const int* __restrict__ edges) {
    int e = blockIdx.x * blockDim.x + threadIdx.x;
    if (e >= E_EDGES) return;
    int s = edges[e];
    int d = edges[E_EDGES + e];
    if (s != d && (unsigned)s < N_NODES && (unsigned)d < N_NODES) {
        atomicAdd(&g_deg[s], 1);
        atomicAdd(&g_indeg[d], 1);
    }
}

__global__ void dinv_kernel() {
    int i = blockIdx.x * blockDim.x + threadIdx.x;
    if (i >= N_NODES) return;
    int dg = g_deg[i];
    g_dinv[i] = (dg > 0) ? rsqrtf((float)dg) : 0.0f;
}

// ------- exclusive scan of g_indeg -> g_rowptr (3 kernels) -------
__global__ void scan1_kernel(int n) {
    __shared__ int s[1024];
    int i = blockIdx.x * 1024 + threadIdx.x;
    int v = (i < n) ? g_indeg[i] : 0;
    s[threadIdx.x] = v;
    __syncthreads();
    for (int off = 1; off < 1024; off <<= 1) {
        int t = (threadIdx.x >= off) ? s[threadIdx.x - off] : 0;
        __syncthreads();
        s[threadIdx.x] += t;
        __syncthreads();
    }
    if (i < n) g_tmp[i] = s[threadIdx.x];
    if (threadIdx.x == 1023) g_btot[blockIdx.x] = s[1023];
}

__global__ void scan2_kernel(int nb) {
    if (threadIdx.x == 0 && blockIdx.x == 0) {
        int run = 0;
        for (int b = 0; b < nb; ++b) { g_boff[b] = run; run += g_btot[b]; }
    }
}

__global__ void scan3_kernel(int n) {
    int i = blockIdx.x * 1024 + threadIdx.x;
    if (i < n) {
        int v = g_tmp[i] + g_boff[blockIdx.x];
        g_rowptr[i + 1] = v;
        if (i + 1 < N_NODES) g_cursor[i + 1] = v;
        if (i == 0) { g_rowptr[0] = 0; g_cursor[0] = 0; }
    }
}

// scatter edges into CSR-by-dst with packed (w, src)
__global__ void scatter_kernel(const int* __restrict__ edges) {
    int e = blockIdx.x * blockDim.x + threadIdx.x;
    if (e >= E_EDGES) return;
    int s = edges[e];
    int d = edges[E_EDGES + e];
    if (s != d && (unsigned)s < N_NODES && (unsigned)d < N_NODES) {
        float w = -(g_dinv[s] * g_dinv[d]);
        int pos = atomicAdd(&g_cursor[d], 1);
        g_colw[pos] = ((long long)(unsigned long long)__float_as_uint(w) << 32)
                      | (unsigned long long)(unsigned)s;
    }
}

// ---------------- GEMM1: xh = relu(feature @ W1 + b1) ----------------
// block tile 64 rows x 64 cols (all), BK=16, 256 threads, 4x4 microtile
__global__ __launch_bounds__(256) void gemm1_kernel(const float* __restrict__ feat,
                                                    const float* __restrict__ W1,
                                                    const float* __restrict__ b1) {
    __shared__ __align__(16) float As[16 * 65];
    __shared__ __align__(16) float Ws[16 * 64];
    int tid = threadIdx.x;
    int tx = tid & 15, ty = tid >> 4;
    int row0 = blockIdx.x * 64;
    int kkA = tid & 15;
    int rA = (tid >> 4) * 4;
    float acc[4][4] = {};

    for (int k0 = 0; k0 < F_IN; k0 += 16) {
        bool kok = (k0 + kkA) < F_IN;
#pragma unroll
        for (int i = 0; i < 4; ++i) {
            int r = row0 + rA + i;
            float v = 0.0f;
            if (r < N_NODES && kok) v = feat[r * F_IN + k0 + kkA];
            As[kkA * 65 + rA + i] = v;
        }
        {
            int L = tid * 4;
            int kk = L >> 6;
            int n = L & 63;
            float4 w4 = make_float4(0.f, 0.f, 0.f, 0.f);
            if (k0 + kk < F_IN) w4 = *(const float4*)&W1[(k0 + kk) * HID + n];
            *(float4*)&Ws[kk * 64 + n] = w4;
        }
        __syncthreads();
#pragma unroll
        for (int kk = 0; kk < 16; ++kk) {
            float a0 = As[kk * 65 + ty * 4 + 0];
            float a1 = As[kk * 65 + ty * 4 + 1];
            float a2 = As[kk * 65 + ty * 4 + 2];
            float a3 = As[kk * 65 + ty * 4 + 3];
            float4 b = *(const float4*)&Ws[kk * 64 + tx * 4];
            acc[0][0] = fmaf(a0, b.x, acc[0][0]); acc[0][1] = fmaf(a0, b.y, acc[0][1]);
            acc[0][2] = fmaf(a0, b.z, acc[0][2]); acc[0][3] = fmaf(a0, b.w, acc[0][3]);
            acc[1][0] = fmaf(a1, b.x, acc[1][0]); acc[1][1] = fmaf(a1, b.y, acc[1][1]);
            acc[1][2] = fmaf(a1, b.z, acc[1][2]); acc[1][3] = fmaf(a1, b.w, acc[1][3]);
            acc[2][0] = fmaf(a2, b.x, acc[2][0]); acc[2][1] = fmaf(a2, b.y, acc[2][1]);
            acc[2][2] = fmaf(a2, b.z, acc[2][2]); acc[2][3] = fmaf(a2, b.w, acc[2][3]);
            acc[3][0] = fmaf(a3, b.x, acc[3][0]); acc[3][1] = fmaf(a3, b.y, acc[3][1]);
            acc[3][2] = fmaf(a3, b.z, acc[3][2]); acc[3][3] = fmaf(a3, b.w, acc[3][3]);
        }
        __syncthreads();
    }
#pragma unroll
    for (int i = 0; i < 4; ++i) {
        int r = row0 + ty * 4 + i;
        if (r >= N_NODES) continue;
#pragma unroll
        for (int j = 0; j < 4; ++j) {
            int c = tx * 4 + j;
            float v = acc[i][j] + __ldg(&b1[c]);
            g_xh[r * HID + c] = fmaxf(v, 0.0f);
        }
    }
}

// ---------------- GEMM2: xc = xh @ W2 + b2 ; hidden = coeff[0]*xc ----------------
__global__ __launch_bounds__(256) void gemm2_kernel(const float* __restrict__ W2,
                                                    const float* __restrict__ b2) {
    __shared__ __align__(16) float As[16 * 65];
    __shared__ __align__(16) float Ws[16 * 64];
    int tid = threadIdx.x;
    int tx = tid & 15, ty = tid >> 4;
    int row0 = blockIdx.x * 64;
    int kkA = tid & 15;
    int rA = (tid >> 4) * 4;
    float acc[4][4] = {};

    for (int k0 = 0; k0 < HID; k0 += 16) {
#pragma unroll
        for (int i = 0; i < 4; ++i) {
            int r = row0 + rA + i;
            float v = 0.0f;
            if (r < N_NODES) v = g_xh[r * HID + k0 + kkA];
            As[kkA * 65 + rA + i] = v;
        }
        {
            int L = tid * 4;
            int kk = L >> 6;
            int n = L & 63;
            float4 w4 = *(const float4*)&W2[(k0 + kk) * CCH + n];
            *(float4*)&Ws[kk * 64 + n] = w4;
        }
        __syncthreads();
#pragma unroll
        for (int kk = 0; kk < 16; ++kk) {
            float a0 = As[kk * 65 + ty * 4 + 0];
            float a1 = As[kk * 65 + ty * 4 + 1];
            float a2 = As[kk * 65 + ty * 4 + 2];
            float a3 = As[kk * 65 + ty * 4 + 3];
            float4 b = *(const float4*)&Ws[kk * 64 + tx * 4];
            acc[0][0] = fmaf(a0, b.x, acc[0][0]); acc[0][1] = fmaf(a0, b.y, acc[0][1]);
            acc[0][2] = fmaf(a0, b.z, acc[0][2]); acc[0][3] = fmaf(a0, b.w, acc[0][3]);
            acc[1][0] = fmaf(a1, b.x, acc[1][0]); acc[1][1] = fmaf(a1, b.y, acc[1][1]);
            acc[1][2] = fmaf(a1, b.z, acc[1][2]); acc[1][3] = fmaf(a1, b.w, acc[1][3]);
            acc[2][0] = fmaf(a2, b.x, acc[2][0]); acc[2][1] = fmaf(a2, b.y, acc[2][1]);
            acc[2][2] = fmaf(a2, b.z, acc[2][2]); acc[2][3] = fmaf(a2, b.w, acc[2][3]);
            acc[3][0] = fmaf(a3, b.x, acc[3][0]); acc[3][1] = fmaf(a3, b.y, acc[3][1]);
            acc[3][2] = fmaf(a3, b.z, acc[3][2]); acc[3][3] = fmaf(a3, b.w, acc[3][3]);
        }
        __syncthreads();
    }
    float c0 = g_coeff[0];
#pragma unroll
    for (int i = 0; i < 4; ++i) {
        int r = row0 + ty * 4 + i;
        if (r >= N_NODES) continue;
#pragma unroll
        for (int j = 0; j < 4; ++j) {
            int c = tx * 4 + j;
            float v = acc[i][j] + __ldg(&b2[c]);
            g_xc[r * CCH + c] = v;
            g_hidden[r * CCH + c] = c0 * v;
        }
    }
}

// ---------------- diffusion hop: tout[row] = sum_e w*tin[src]; hidden += c_d*tout ----------------
// one warp per dst row; each lane owns 2 channels as float2
__global__ __launch_bounds__(256) void hop_kernel(int d) {
    int row = blockIdx.x * 8 + (threadIdx.x >> 5);
    if (row >= N_NODES) return;
    int lane = threadIdx.x & 31;

    const float* tin = (d == 1) ? g_xc : (((d & 1) == 0) ? g_bufA : g_bufB);
    float* tout = (d & 1) ? g_bufA : g_bufB;
    const float2* tin2 = (const float2*)tin;

    int beg = __ldg(&g_rowptr[row]);
    int end = __ldg(&g_rowptr[row + 1]);
    float2 acc = make_float2(0.f, 0.f);
#pragma unroll 4
    for (int j = beg; j < end; ++j) {
        long long m = __ldg(&g_colw[j]);
        int s = (int)(m & 0xFFFFFFFFLL);
        float w = __uint_as_float((unsigned)(((unsigned long long)m) >> 32));
        float2 v = __ldg(&tin2[s * 32 + lane]);
        acc.x = fmaf(w, v.x, acc.x);
        acc.y = fmaf(w, v.y, acc.y);
    }
    int idx = row * 32 + lane;
    ((float2*)tout)[idx] = acc;
    float c = g_coeff[d];
    float2 h = ((float2*)g_hidden)[idx];
    h.x = fmaf(c, acc.x, h.x);
    h.y = fmaf(c, acc.y, h.y);
    ((float2*)g_hidden)[idx] = h;
}

// ---------------- final: out = log_softmax(hidden + xc) ----------------
__global__ __launch_bounds__(256) void final_kernel(float* __restrict__ out) {
    int row = blockIdx.x * 8 + (threadIdx.x >> 5);
    if (row >= N_NODES) return;
    int lane = threadIdx.x & 31;
    int idx = row * 32 + lane;
    float2 v = ((const float2*)g_xc)[idx];
    float2 h = ((const float2*)g_hidden)[idx];
    v.x += h.x; v.y += h.y;
    float m = fmaxf(v.x, v.y);
#pragma unroll
    for (int o = 16; o; o >>= 1) m = fmaxf(m, __shfl_xor_sync(0xFFFFFFFFu, m, o));
    float s = expf(v.x - m) + expf(v.y - m);
#pragma unroll
    for (int o = 16; o; o >>= 1) s += __shfl_xor_sync(0xFFFFFFFFu, s, o);
    float l = m + logf(s);
    ((float2*)out)[idx] = make_float2(v.x - l, v.y - l);
}

// ---------------- launch ----------------
extern "C" void kernel_launch(void* const* d_in, const int* in_sizes, int n_in,
                              void* d_out, int out_size) {
    const float* feature    = (const float*)d_in[0];
    const int*   edges      = (const int*)d_in[1];   // int32 (jax x64 disabled)
    const float* W1         = (const float*)d_in[2];
    const float* b1         = (const float*)d_in[3];
    const float* W2         = (const float*)d_in[4];
    const float* b2         = (const float*)d_in[5];
    const float* alpha      = (const float*)d_in[6];
    const float* beta       = (const float*)d_in[7];
    float* out              = (float*)d_out;

    const int TB = 256;
    int gN   = (N_NODES + TB - 1) / TB;        // 391
    int gE   = (E_EDGES + TB - 1) / TB;        // 12500
    int gRow = (N_NODES + 7) / 8;              // 12500 (warp-per-row kernels)
    int gG   = (N_NODES + 63) / 64;            // 1563
    int nb   = (N_NODES + 1023) / 1024;        // 98

    zero_counts_kernel<<<gN, TB>>>();
    coeff_kernel<<<1, 32>>>(alpha, beta);
    pass1_kernel<<<gE, TB>>>(edges);
    dinv_kernel<<<gN, TB>>>();
    scan1_kernel<<<nb, 1024>>>(N_NODES);
    scan2_kernel<<<1, 32>>>(nb);
    scan3_kernel<<<nb, 1024>>>(N_NODES);
    scatter_kernel<<<gE, TB>>>(edges);

    gemm1_kernel<<<gG, TB>>>(feature, W1, b1);
    gemm2_kernel<<<gG, TB>>>(W2, b2);

    for (int d = 1; d <= DORD; ++d)
        hop_kernel<<<gRow, TB>>>(d);

    final_kernel<<<gRow, TB>>>(out);
}

// round 6
// speedup vs baseline: 1.1201x; 1.1201x over previous
#include <cuda_runtime.h>
#include <cuda_fp16.h>
#include <math.h>

#define N_NODES 100000
#define E_EDGES 3200000
#define F_IN    500
#define HID     64
#define CCH     64
#define KFREQ   5
#define DORD    10

// ---------------- scratch (static device globals; no allocation) ----------------
__device__ __align__(16) float  g_xh[N_NODES * HID];     // relu(feature@W1+b1)
__device__ __align__(16) float  g_xc[N_NODES * CCH];     // lin2 output fp32 ("x" added at end)
__device__ __align__(16) __half g_xc16[N_NODES * CCH];   // fp16 copy for hop-1 gather
__device__ __align__(16) __half g_h16A[N_NODES * CCH];   // fp16 diffusion ping
__device__ __align__(16) __half g_h16B[N_NODES * CCH];   // fp16 diffusion pong
__device__ __align__(16) float  g_hidden[N_NODES * CCH]; // fp32 accumulator
__device__ __align__(16) long long g_colw[E_EDGES];      // packed {w(float hi32), src(lo32)}
__device__ int    g_deg[N_NODES];
__device__ int    g_indeg[N_NODES];
__device__ float  g_dinv[N_NODES];
__device__ int    g_rowptr[N_NODES + 1];
__device__ int    g_cursor[N_NODES + 1];
__device__ int    g_tmp[N_NODES];
__device__ int    g_btot[128];
__device__ int    g_boff[128];
__device__ float  g_coeff[16];

// ---------------- small utility kernels ----------------
__global__ void zero_counts_kernel() {
    int i = blockIdx.x * blockDim.x + threadIdx.x;
    if (i < N_NODES) { g_deg[i] = 0; g_indeg[i] = 0; }
}

// coeff[d] = sum_k alpha[k]*SINC[k][d] + beta[k]*COSC[k][d] (tables in fp64, cast)
__global__ void coeff_kernel(const float* __restrict__ alpha,
                             const float* __restrict__ beta) {
    int d = threadIdx.x;
    if (d > DORD) return;
    float acc = 0.0f;
    for (int k = 0; k < KFREQ; ++k) {
        double x = (double)(k + 1) * 3.14159265358979323846;
        double p = 1.0;
        for (int i = 0; i < d; ++i) p *= x;
        double f = 1.0;
        for (int i = 2; i <= d; ++i) f *= (double)i;
        double sinc = 0.0, cosc = 0.0;
        if ((d & 1) == 0) {
            double sgn = (((d / 2) & 1) == 0) ? 1.0 : -1.0;
            cosc = sgn * p / f;
        } else {
            double sgn = ((((d - 1) / 2) & 1) == 0) ? 1.0 : -1.0;
            sinc = sgn * p / f;
        }
        acc += alpha[k] * (float)sinc + beta[k] * (float)cosc;
    }
    g_coeff[d] = acc;
}

// edges buffer is int32 (jax x64 disabled)
__global__ void pass1_kernel(const int* __restrict__ edges) {
    int e = blockIdx.x * blockDim.x + threadIdx.x;
    if (e >= E_EDGES) return;
    int s = edges[e];
    int d = edges[E_EDGES + e];
    if (s != d && (unsigned)s < N_NODES && (unsigned)d < N_NODES) {
        atomicAdd(&g_deg[s], 1);
        atomicAdd(&g_indeg[d], 1);
    }
}

__global__ void dinv_kernel() {
    int i = blockIdx.x * blockDim.x + threadIdx.x;
    if (i >= N_NODES) return;
    int dg = g_deg[i];
    g_dinv[i] = (dg > 0) ? rsqrtf((float)dg) : 0.0f;
}

// ------- exclusive scan of g_indeg -> g_rowptr -------
__global__ void scan1_kernel(int n) {
    __shared__ int s[1024];
    int i = blockIdx.x * 1024 + threadIdx.x;
    int v = (i < n) ? g_indeg[i] : 0;
    s[threadIdx.x] = v;
    __syncthreads();
    for (int off = 1; off < 1024; off <<= 1) {
        int t = (threadIdx.x >= off) ? s[threadIdx.x - off] : 0;
        __syncthreads();
        s[threadIdx.x] += t;
        __syncthreads();
    }
    if (i < n) g_tmp[i] = s[threadIdx.x];
    if (threadIdx.x == 1023) g_btot[blockIdx.x] = s[1023];
}

__global__ void scan2_kernel(int nb) {
    if (threadIdx.x == 0 && blockIdx.x == 0) {
        int run = 0;
        for (int b = 0; b < nb; ++b) { g_boff[b] = run; run += g_btot[b]; }
    }
}

__global__ void scan3_kernel(int n) {
    int i = blockIdx.x * 1024 + threadIdx.x;
    if (i < n) {
        int v = g_tmp[i] + g_boff[blockIdx.x];
        g_rowptr[i + 1] = v;
        if (i + 1 < N_NODES) g_cursor[i + 1] = v;
        if (i == 0) { g_rowptr[0] = 0; g_cursor[0] = 0; }
    }
}

__global__ void scatter_kernel(const int* __restrict__ edges) {
    int e = blockIdx.x * blockDim.x + threadIdx.x;
    if (e >= E_EDGES) return;
    int s = edges[e];
    int d = edges[E_EDGES + e];
    if (s != d && (unsigned)s < N_NODES && (unsigned)d < N_NODES) {
        float w = -(g_dinv[s] * g_dinv[d]);
        int pos = atomicAdd(&g_cursor[d], 1);
        g_colw[pos] = ((long long)(unsigned long long)__float_as_uint(w) << 32)
                      | (unsigned long long)(unsigned)s;
    }
}

// ---------------- packed f32x2 FMA helper ----------------
__device__ __forceinline__ void ffma2(unsigned long long& acc,
                                      unsigned long long a,
                                      unsigned long long b) {
    asm("fma.rn.f32x2 %0, %1, %2, %0;" : "+l"(acc) : "l"(a), "l"(b));
}
__device__ __forceinline__ float2 unpack2(unsigned long long p) {
    float2 r;
    asm("mov.b64 {%0, %1}, %2;" : "=f"(r.x), "=f"(r.y) : "l"(p));
    return r;
}

// ---------------- GEMM1: xh = relu(feature @ W1 + b1) ----------------
// 64x64 block tile, BK=16, 256 threads, 4x4 microtile via fma.rn.f32x2.
// A stored DUPLICATED in smem as float2{v,v} so packed multiplier = one LDS.64.
__global__ __launch_bounds__(256) void gemm1_kernel(const float* __restrict__ feat,
                                                    const float* __restrict__ W1,
                                                    const float* __restrict__ b1) {
    __shared__ __align__(16) float2 As2[16 * 65];
    __shared__ __align__(16) float  Ws[16 * 64];
    int tid = threadIdx.x;
    int tx = tid & 15, ty = tid >> 4;
    int row0 = blockIdx.x * 64;
    int kkA = tid & 15;
    int rA = (tid >> 4) * 4;
    unsigned long long acc[4][2] = {};   // 2 packed pairs x 4 rows = 16 fp32 accumulators

    for (int k0 = 0; k0 < F_IN; k0 += 16) {
        bool kok = (k0 + kkA) < F_IN;
#pragma unroll
        for (int i = 0; i < 4; ++i) {
            int r = row0 + rA + i;
            float v = 0.0f;
            if (r < N_NODES && kok) v = feat[r * F_IN + k0 + kkA];
            As2[kkA * 65 + rA + i] = make_float2(v, v);
        }
        {
            int L = tid * 4;
            int kk = L >> 6;
            int n = L & 63;
            float4 w4 = make_float4(0.f, 0.f, 0.f, 0.f);
            if (k0 + kk < F_IN) w4 = *(const float4*)&W1[(k0 + kk) * HID + n];
            *(float4*)&Ws[kk * 64 + n] = w4;
        }
        __syncthreads();
#pragma unroll
        for (int kk = 0; kk < 16; ++kk) {
            ulonglong2 bp = *(const ulonglong2*)&Ws[kk * 64 + tx * 4];
            const unsigned long long* ap =
                (const unsigned long long*)&As2[kk * 65 + ty * 4];
#pragma unroll
            for (int i = 0; i < 4; ++i) {
                unsigned long long a = ap[i];
                ffma2(acc[i][0], a, bp.x);
                ffma2(acc[i][1], a, bp.y);
            }
        }
        __syncthreads();
    }
#pragma unroll
    for (int i = 0; i < 4; ++i) {
        int r = row0 + ty * 4 + i;
        if (r >= N_NODES) continue;
        float2 p0 = unpack2(acc[i][0]);
        float2 p1 = unpack2(acc[i][1]);
        int c = tx * 4;
        g_xh[r * HID + c + 0] = fmaxf(p0.x + __ldg(&b1[c + 0]), 0.0f);
        g_xh[r * HID + c + 1] = fmaxf(p0.y + __ldg(&b1[c + 1]), 0.0f);
        g_xh[r * HID + c + 2] = fmaxf(p1.x + __ldg(&b1[c + 2]), 0.0f);
        g_xh[r * HID + c + 3] = fmaxf(p1.y + __ldg(&b1[c + 3]), 0.0f);
    }
}

// ---------------- GEMM2: xc = xh @ W2 + b2 ; hidden = c0*xc ; xc16 = fp16(xc) ----------------
__global__ __launch_bounds__(256) void gemm2_kernel(const float* __restrict__ W2,
                                                    const float* __restrict__ b2) {
    __shared__ __align__(16) float2 As2[16 * 65];
    __shared__ __align__(16) float  Ws[16 * 64];
    int tid = threadIdx.x;
    int tx = tid & 15, ty = tid >> 4;
    int row0 = blockIdx.x * 64;
    int kkA = tid & 15;
    int rA = (tid >> 4) * 4;
    unsigned long long acc[4][2] = {};

    for (int k0 = 0; k0 < HID; k0 += 16) {
#pragma unroll
        for (int i = 0; i < 4; ++i) {
            int r = row0 + rA + i;
            float v = 0.0f;
            if (r < N_NODES) v = g_xh[r * HID + k0 + kkA];
            As2[kkA * 65 + rA + i] = make_float2(v, v);
        }
        {
            int L = tid * 4;
            int kk = L >> 6;
            int n = L & 63;
            float4 w4 = *(const float4*)&W2[(k0 + kk) * CCH + n];
            *(float4*)&Ws[kk * 64 + n] = w4;
        }
        __syncthreads();
#pragma unroll
        for (int kk = 0; kk < 16; ++kk) {
            ulonglong2 bp = *(const ulonglong2*)&Ws[kk * 64 + tx * 4];
            const unsigned long long* ap =
                (const unsigned long long*)&As2[kk * 65 + ty * 4];
#pragma unroll
            for (int i = 0; i < 4; ++i) {
                unsigned long long a = ap[i];
                ffma2(acc[i][0], a, bp.x);
                ffma2(acc[i][1], a, bp.y);
            }
        }
        __syncthreads();
    }
    float c0 = g_coeff[0];
#pragma unroll
    for (int i = 0; i < 4; ++i) {
        int r = row0 + ty * 4 + i;
        if (r >= N_NODES) continue;
        float2 p0 = unpack2(acc[i][0]);
        float2 p1 = unpack2(acc[i][1]);
        int c = tx * 4;
        float v0 = p0.x + __ldg(&b2[c + 0]);
        float v1 = p0.y + __ldg(&b2[c + 1]);
        float v2 = p1.x + __ldg(&b2[c + 2]);
        float v3 = p1.y + __ldg(&b2[c + 3]);
        float* xr = &g_xc[r * CCH + c];
        xr[0] = v0; xr[1] = v1; xr[2] = v2; xr[3] = v3;
        float* hr = &g_hidden[r * CCH + c];
        hr[0] = c0 * v0; hr[1] = c0 * v1; hr[2] = c0 * v2; hr[3] = c0 * v3;
        __half2* x16 = (__half2*)&g_xc16[r * CCH + c];
        x16[0] = __floats2half2_rn(v0, v1);
        x16[1] = __floats2half2_rn(v2, v3);
    }
}

// ---------------- diffusion hop (fp16 state, fp32 accumulate) ----------------
// one warp per dst row; each lane owns 2 channels as half2
__global__ __launch_bounds__(256) void hop_kernel(int d) {
    int row = blockIdx.x * 8 + (threadIdx.x >> 5);
    if (row >= N_NODES) return;
    int lane = threadIdx.x & 31;

    const __half2* tin = (d == 1) ? (const __half2*)g_xc16
                        : ((d & 1) ? (const __half2*)g_h16B : (const __half2*)g_h16A);
    __half2* tout = (d & 1) ? (__half2*)g_h16A : (__half2*)g_h16B;

    int beg = __ldg(&g_rowptr[row]);
    int end = __ldg(&g_rowptr[row + 1]);
    float2 acc = make_float2(0.f, 0.f);
#pragma unroll 4
    for (int j = beg; j < end; ++j) {
        long long m = __ldg(&g_colw[j]);
        int s = (int)(m & 0xFFFFFFFFLL);
        float w = __uint_as_float((unsigned)(((unsigned long long)m) >> 32));
        float2 v = __half22float2(__ldg(&tin[s * 32 + lane]));
        acc.x = fmaf(w, v.x, acc.x);
        acc.y = fmaf(w, v.y, acc.y);
    }
    int idx = row * 32 + lane;
    tout[idx] = __floats2half2_rn(acc.x, acc.y);
    float c = g_coeff[d];
    float2 h = ((float2*)g_hidden)[idx];
    h.x = fmaf(c, acc.x, h.x);
    h.y = fmaf(c, acc.y, h.y);
    ((float2*)g_hidden)[idx] = h;
}

// ---------------- final: out = log_softmax(hidden + xc) ----------------
__global__ __launch_bounds__(256) void final_kernel(float* __restrict__ out) {
    int row = blockIdx.x * 8 + (threadIdx.x >> 5);
    if (row >= N_NODES) return;
    int lane = threadIdx.x & 31;
    int idx = row * 32 + lane;
    float2 v = ((const float2*)g_xc)[idx];
    float2 h = ((const float2*)g_hidden)[idx];
    v.x += h.x; v.y += h.y;
    float m = fmaxf(v.x, v.y);
#pragma unroll
    for (int o = 16; o; o >>= 1) m = fmaxf(m, __shfl_xor_sync(0xFFFFFFFFu, m, o));
    float s = expf(v.x - m) + expf(v.y - m);
#pragma unroll
    for (int o = 16; o; o >>= 1) s += __shfl_xor_sync(0xFFFFFFFFu, s, o);
    float l = m + logf(s);
    ((float2*)out)[idx] = make_float2(v.x - l, v.y - l);
}

// ---------------- launch ----------------
extern "C" void kernel_launch(void* const* d_in, const int* in_sizes, int n_in,
                              void* d_out, int out_size) {
    const float* feature = (const float*)d_in[0];
    const int*   edges   = (const int*)d_in[1];   // int32
    const float* W1      = (const float*)d_in[2];
    const float* b1      = (const float*)d_in[3];
    const float* W2      = (const float*)d_in[4];
    const float* b2      = (const float*)d_in[5];
    const float* alpha   = (const float*)d_in[6];
    const float* beta    = (const float*)d_in[7];
    float* out           = (float*)d_out;

    const int TB = 256;
    int gN   = (N_NODES + TB - 1) / TB;
    int gE   = (E_EDGES + TB - 1) / TB;
    int gRow = (N_NODES + 7) / 8;
    int gG   = (N_NODES + 63) / 64;
    int nb   = (N_NODES + 1023) / 1024;

    zero_counts_kernel<<<gN, TB>>>();
    coeff_kernel<<<1, 32>>>(alpha, beta);
    pass1_kernel<<<gE, TB>>>(edges);
    dinv_kernel<<<gN, TB>>>();
    scan1_kernel<<<nb, 1024>>>(N_NODES);
    scan2_kernel<<<1, 32>>>(nb);
    scan3_kernel<<<nb, 1024>>>(N_NODES);
    scatter_kernel<<<gE, TB>>>(edges);

    gemm1_kernel<<<gG, TB>>>(feature, W1, b1);
    gemm2_kernel<<<gG, TB>>>(W2, b2);

    for (int d = 1; d <= DORD; ++d)
        hop_kernel<<<gRow, TB>>>(d);

    final_kernel<<<gRow, TB>>>(out);
}

// round 8
// speedup vs baseline: 1.1869x; 1.0596x over previous
#include <cuda_runtime.h>
#include <cuda_fp16.h>
#include <math.h>

#define N_NODES 100000
#define E_EDGES 3200000
#define F_IN    500
#define HID     64
#define CCH     64
#define KFREQ   5
#define DORD    10

// ---------------- scratch (static device globals; no allocation) ----------------
__device__ __align__(16) float  g_xh[N_NODES * HID];     // relu(feature@W1+b1)
__device__ __align__(16) float  g_xc[N_NODES * CCH];     // lin2 output fp32 ("x" added at end)
__device__ __align__(16) __half g_xc16[N_NODES * CCH];   // fp16 copy for hop-1 gather
__device__ __align__(16) __half g_h16A[N_NODES * CCH];   // fp16 diffusion ping (odd-d outputs)
__device__ __align__(16) __half g_h16B[N_NODES * CCH];   // fp16 diffusion pong (even-d outputs)
__device__ __align__(16) float  g_hidden[N_NODES * CCH]; // fp32 accumulator
__device__ __align__(16) long long g_colw[E_EDGES];      // packed {w(float hi32), src(lo32)}
__device__ int    g_deg[N_NODES];
__device__ int    g_indeg[N_NODES];
__device__ float  g_dinv[N_NODES];
__device__ int    g_rowptr[N_NODES + 1];
__device__ int    g_cursor[N_NODES + 1];
__device__ int    g_tmp[N_NODES];
__device__ int    g_btot[128];
__device__ int    g_boff[128];
__device__ float  g_coeff[16];

// ---------------- small utility kernels ----------------
__global__ void zero_counts_kernel() {
    int i = blockIdx.x * blockDim.x + threadIdx.x;
    if (i < N_NODES) { g_deg[i] = 0; g_indeg[i] = 0; }
}

// coeff[d] = sum_k alpha[k]*SINC[k][d] + beta[k]*COSC[k][d] (tables in fp64, cast)
__global__ void coeff_kernel(const float* __restrict__ alpha,
                             const float* __restrict__ beta) {
    int d = threadIdx.x;
    if (d > DORD) return;
    float acc = 0.0f;
    for (int k = 0; k < KFREQ; ++k) {
        double x = (double)(k + 1) * 3.14159265358979323846;
        double p = 1.0;
        for (int i = 0; i < d; ++i) p *= x;
        double f = 1.0;
        for (int i = 2; i <= d; ++i) f *= (double)i;
        double sinc = 0.0, cosc = 0.0;
        if ((d & 1) == 0) {
            double sgn = (((d / 2) & 1) == 0) ? 1.0 : -1.0;
            cosc = sgn * p / f;
        } else {
            double sgn = ((((d - 1) / 2) & 1) == 0) ? 1.0 : -1.0;
            sinc = sgn * p / f;
        }
        acc += alpha[k] * (float)sinc + beta[k] * (float)cosc;
    }
    g_coeff[d] = acc;
}

// edges buffer is int32 (jax x64 disabled)
__global__ void pass1_kernel(const int* __restrict__ edges) {
    int e = blockIdx.x * blockDim.x + threadIdx.x;
    if (e >= E_EDGES) return;
    int s = edges[e];
    int d = edges[E_EDGES + e];
    if (s != d && (unsigned)s < N_NODES && (unsigned)d < N_NODES) {
        atomicAdd(&g_deg[s], 1);
        atomicAdd(&g_indeg[d], 1);
    }
}

__global__ void dinv_kernel() {
    int i = blockIdx.x * blockDim.x + threadIdx.x;
    if (i >= N_NODES) return;
    int dg = g_deg[i];
    g_dinv[i] = (dg > 0) ? rsqrtf((float)dg) : 0.0f;
}

// ------- exclusive scan of g_indeg -> g_rowptr -------
__global__ void scan1_kernel(int n) {
    __shared__ int s[1024];
    int i = blockIdx.x * 1024 + threadIdx.x;
    int v = (i < n) ? g_indeg[i] : 0;
    s[threadIdx.x] = v;
    __syncthreads();
    for (int off = 1; off < 1024; off <<= 1) {
        int t = (threadIdx.x >= off) ? s[threadIdx.x - off] : 0;
        __syncthreads();
        s[threadIdx.x] += t;
        __syncthreads();
    }
    if (i < n) g_tmp[i] = s[threadIdx.x];
    if (threadIdx.x == 1023) g_btot[blockIdx.x] = s[1023];
}

__global__ void scan2_kernel(int nb) {
    if (threadIdx.x == 0 && blockIdx.x == 0) {
        int run = 0;
        for (int b = 0; b < nb; ++b) { g_boff[b] = run; run += g_btot[b]; }
    }
}

__global__ void scan3_kernel(int n) {
    int i = blockIdx.x * 1024 + threadIdx.x;
    if (i < n) {
        int v = g_tmp[i] + g_boff[blockIdx.x];
        g_rowptr[i + 1] = v;
        if (i + 1 < N_NODES) g_cursor[i + 1] = v;
        if (i == 0) { g_rowptr[0] = 0; g_cursor[0] = 0; }
    }
}

__global__ void scatter_kernel(const int* __restrict__ edges) {
    int e = blockIdx.x * blockDim.x + threadIdx.x;
    if (e >= E_EDGES) return;
    int s = edges[e];
    int d = edges[E_EDGES + e];
    if (s != d && (unsigned)s < N_NODES && (unsigned)d < N_NODES) {
        float w = -(g_dinv[s] * g_dinv[d]);
        int pos = atomicAdd(&g_cursor[d], 1);
        g_colw[pos] = ((long long)(unsigned long long)__float_as_uint(w) << 32)
                      | (unsigned long long)(unsigned)s;
    }
}

// ---------------- packed f32x2 FMA helper ----------------
__device__ __forceinline__ void ffma2(unsigned long long& acc,
                                      unsigned long long a,
                                      unsigned long long b) {
    asm("fma.rn.f32x2 %0, %1, %2, %0;" : "+l"(acc) : "l"(a), "l"(b));
}
__device__ __forceinline__ float2 unpack2(unsigned long long p) {
    float2 r;
    asm("mov.b64 {%0, %1}, %2;" : "=f"(r.x), "=f"(r.y) : "l"(p));
    return r;
}

// ---------------- GEMM1: xh = relu(feature @ W1 + b1) ----------------
__global__ __launch_bounds__(256) void gemm1_kernel(const float* __restrict__ feat,
                                                    const float* __restrict__ W1,
                                                    const float* __restrict__ b1) {
    __shared__ __align__(16) float2 As2[16 * 65];
    __shared__ __align__(16) float  Ws[16 * 64];
    int tid = threadIdx.x;
    int tx = tid & 15, ty = tid >> 4;
    int row0 = blockIdx.x * 64;
    int kkA = tid & 15;
    int rA = (tid >> 4) * 4;
    unsigned long long acc[4][2] = {};

    for (int k0 = 0; k0 < F_IN; k0 += 16) {
        bool kok = (k0 + kkA) < F_IN;
#pragma unroll
        for (int i = 0; i < 4; ++i) {
            int r = row0 + rA + i;
            float v = 0.0f;
            if (r < N_NODES && kok) v = feat[r * F_IN + k0 + kkA];
            As2[kkA * 65 + rA + i] = make_float2(v, v);
        }
        {
            int L = tid * 4;
            int kk = L >> 6;
            int n = L & 63;
            float4 w4 = make_float4(0.f, 0.f, 0.f, 0.f);
            if (k0 + kk < F_IN) w4 = *(const float4*)&W1[(k0 + kk) * HID + n];
            *(float4*)&Ws[kk * 64 + n] = w4;
        }
        __syncthreads();
#pragma unroll
        for (int kk = 0; kk < 16; ++kk) {
            ulonglong2 bp = *(const ulonglong2*)&Ws[kk * 64 + tx * 4];
            const unsigned long long* ap =
                (const unsigned long long*)&As2[kk * 65 + ty * 4];
#pragma unroll
            for (int i = 0; i < 4; ++i) {
                unsigned long long a = ap[i];
                ffma2(acc[i][0], a, bp.x);
                ffma2(acc[i][1], a, bp.y);
            }
        }
        __syncthreads();
    }
#pragma unroll
    for (int i = 0; i < 4; ++i) {
        int r = row0 + ty * 4 + i;
        if (r >= N_NODES) continue;
        float2 p0 = unpack2(acc[i][0]);
        float2 p1 = unpack2(acc[i][1]);
        int c = tx * 4;
        g_xh[r * HID + c + 0] = fmaxf(p0.x + __ldg(&b1[c + 0]), 0.0f);
        g_xh[r * HID + c + 1] = fmaxf(p0.y + __ldg(&b1[c + 1]), 0.0f);
        g_xh[r * HID + c + 2] = fmaxf(p1.x + __ldg(&b1[c + 2]), 0.0f);
        g_xh[r * HID + c + 3] = fmaxf(p1.y + __ldg(&b1[c + 3]), 0.0f);
    }
}

// ---------------- GEMM2: xc = xh @ W2 + b2 ; hidden = c0*xc ; xc16 = fp16(xc) ----------------
__global__ __launch_bounds__(256) void gemm2_kernel(const float* __restrict__ W2,
                                                    const float* __restrict__ b2) {
    __shared__ __align__(16) float2 As2[16 * 65];
    __shared__ __align__(16) float  Ws[16 * 64];
    int tid = threadIdx.x;
    int tx = tid & 15, ty = tid >> 4;
    int row0 = blockIdx.x * 64;
    int kkA = tid & 15;
    int rA = (tid >> 4) * 4;
    unsigned long long acc[4][2] = {};

    for (int k0 = 0; k0 < HID; k0 += 16) {
#pragma unroll
        for (int i = 0; i < 4; ++i) {
            int r = row0 + rA + i;
            float v = 0.0f;
            if (r < N_NODES) v = g_xh[r * HID + k0 + kkA];
            As2[kkA * 65 + rA + i] = make_float2(v, v);
        }
        {
            int L = tid * 4;
            int kk = L >> 6;
            int n = L & 63;
            float4 w4 = *(const float4*)&W2[(k0 + kk) * CCH + n];
            *(float4*)&Ws[kk * 64 + n] = w4;
        }
        __syncthreads();
#pragma unroll
        for (int kk = 0; kk < 16; ++kk) {
            ulonglong2 bp = *(const ulonglong2*)&Ws[kk * 64 + tx * 4];
            const unsigned long long* ap =
                (const unsigned long long*)&As2[kk * 65 + ty * 4];
#pragma unroll
            for (int i = 0; i < 4; ++i) {
                unsigned long long a = ap[i];
                ffma2(acc[i][0], a, bp.x);
                ffma2(acc[i][1], a, bp.y);
            }
        }
        __syncthreads();
    }
    float c0 = g_coeff[0];
#pragma unroll
    for (int i = 0; i < 4; ++i) {
        int r = row0 + ty * 4 + i;
        if (r >= N_NODES) continue;
        float2 p0 = unpack2(acc[i][0]);
        float2 p1 = unpack2(acc[i][1]);
        int c = tx * 4;
        float v0 = p0.x + __ldg(&b2[c + 0]);
        float v1 = p0.y + __ldg(&b2[c + 1]);
        float v2 = p1.x + __ldg(&b2[c + 2]);
        float v3 = p1.y + __ldg(&b2[c + 3]);
        float* xr = &g_xc[r * CCH + c];
        xr[0] = v0; xr[1] = v1; xr[2] = v2; xr[3] = v3;
        float* hr = &g_hidden[r * CCH + c];
        hr[0] = c0 * v0; hr[1] = c0 * v1; hr[2] = c0 * v2; hr[3] = c0 * v3;
        __half2* x16 = (__half2*)&g_xc16[r * CCH + c];
        x16[0] = __floats2half2_rn(v0, v1);
        x16[1] = __floats2half2_rn(v2, v3);
    }
}

// ---------------- diffusion hop (shfl-staged gathers, fp16 state, fp32 accumulate) ----------------
// One warp per dst row. Warp loads 32 edge records at once (coalesced), broadcasts
// (src,w) via SHFL, then issues 32 independent row-gathers -> MLP ~32 instead of ~4.
__device__ __forceinline__ float2 hop_row_accum(const __half2* __restrict__ tin,
                                                int beg, int end, int lane) {
    float2 acc = make_float2(0.f, 0.f);
    const __half2* tlane = tin + lane;
    int j0 = beg;
    // full 32-edge chunks
    for (; j0 + 32 <= end; j0 += 32) {
        long long m = __ldg(&g_colw[j0 + lane]);
        int      ms = (int)(m & 0xFFFFFFFFLL);
        unsigned mw = (unsigned)(((unsigned long long)m) >> 32);
#pragma unroll
        for (int t = 0; t < 32; ++t) {
            int   s = __shfl_sync(0xFFFFFFFFu, ms, t);
            float w = __uint_as_float(__shfl_sync(0xFFFFFFFFu, mw, t));
            float2 v = __half22float2(__ldg(&tlane[s * 32]));
            acc.x = fmaf(w, v.x, acc.x);
            acc.y = fmaf(w, v.y, acc.y);
        }
    }
    // tail
    int n = end - j0;
    if (n > 0) {
        long long m = (lane < n) ? __ldg(&g_colw[j0 + lane]) : 0LL;
        int      ms = (int)(m & 0xFFFFFFFFLL);
        unsigned mw = (unsigned)(((unsigned long long)m) >> 32);
#pragma unroll 8
        for (int t = 0; t < n; ++t) {
            int   s = __shfl_sync(0xFFFFFFFFu, ms, t);
            float w = __uint_as_float(__shfl_sync(0xFFFFFFFFu, mw, t));
            float2 v = __half22float2(__ldg(&tlane[s * 32]));
            acc.x = fmaf(w, v.x, acc.x);
            acc.y = fmaf(w, v.y, acc.y);
        }
    }
    return acc;
}

// ping-pong convention: hop d reads (d==1 ? xc16 : d odd ? B : A)… concretely
// d odd -> writes A, d even -> writes B. So hop d input = (d-1) output:
//   d==1: xc16;  d even: A (from odd d-1);  d odd>1: B (from even d-1).
__global__ __launch_bounds__(256) void hop_kernel(int d) {
    int row = blockIdx.x * 8 + (threadIdx.x >> 5);
    if (row >= N_NODES) return;
    int lane = threadIdx.x & 31;

    const __half2* tin = (d == 1) ? (const __half2*)g_xc16
                        : ((d & 1) ? (const __half2*)g_h16B : (const __half2*)g_h16A);
    __half2* tout = (d & 1) ? (__half2*)g_h16A : (__half2*)g_h16B;

    int beg = __ldg(&g_rowptr[row]);
    int end = __ldg(&g_rowptr[row + 1]);
    float2 acc = hop_row_accum(tin, beg, end, lane);

    int idx = row * 32 + lane;
    tout[idx] = __floats2half2_rn(acc.x, acc.y);
    float c = g_coeff[d];
    float2 h = ((float2*)g_hidden)[idx];
    h.x = fmaf(c, acc.x, h.x);
    h.y = fmaf(c, acc.y, h.y);
    ((float2*)g_hidden)[idx] = h;
}

// ---------------- last hop (d=10) fused with log_softmax epilogue ----------------
// d=9 is odd -> its output lives in g_h16A. That is the input here. (R7 bug: read B.)
__global__ __launch_bounds__(256) void hop_final_kernel(float* __restrict__ out) {
    int row = blockIdx.x * 8 + (threadIdx.x >> 5);
    if (row >= N_NODES) return;
    int lane = threadIdx.x & 31;

    const __half2* tin = (const __half2*)g_h16A;

    int beg = __ldg(&g_rowptr[row]);
    int end = __ldg(&g_rowptr[row + 1]);
    float2 acc = hop_row_accum(tin, beg, end, lane);

    int idx = row * 32 + lane;
    float c = g_coeff[DORD];
    float2 h = ((const float2*)g_hidden)[idx];
    float2 x = ((const float2*)g_xc)[idx];
    float2 v;
    v.x = fmaf(c, acc.x, h.x) + x.x;
    v.y = fmaf(c, acc.y, h.y) + x.y;
    float m = fmaxf(v.x, v.y);
#pragma unroll
    for (int o = 16; o; o >>= 1) m = fmaxf(m, __shfl_xor_sync(0xFFFFFFFFu, m, o));
    float s = expf(v.x - m) + expf(v.y - m);
#pragma unroll
    for (int o = 16; o; o >>= 1) s += __shfl_xor_sync(0xFFFFFFFFu, s, o);
    float l = m + logf(s);
    ((float2*)out)[idx] = make_float2(v.x - l, v.y - l);
}

// ---------------- launch ----------------
extern "C" void kernel_launch(void* const* d_in, const int* in_sizes, int n_in,
                              void* d_out, int out_size) {
    const float* feature = (const float*)d_in[0];
    const int*   edges   = (const int*)d_in[1];   // int32
    const float* W1      = (const float*)d_in[2];
    const float* b1      = (const float*)d_in[3];
    const float* W2      = (const float*)d_in[4];
    const float* b2      = (const float*)d_in[5];
    const float* alpha   = (const float*)d_in[6];
    const float* beta    = (const float*)d_in[7];
    float* out           = (float*)d_out;

    const int TB = 256;
    int gN   = (N_NODES + TB - 1) / TB;
    int gE   = (E_EDGES + TB - 1) / TB;
    int gRow = (N_NODES + 7) / 8;
    int gG   = (N_NODES + 63) / 64;
    int nb   = (N_NODES + 1023) / 1024;

    zero_counts_kernel<<<gN, TB>>>();
    coeff_kernel<<<1, 32>>>(alpha, beta);
    pass1_kernel<<<gE, TB>>>(edges);
    dinv_kernel<<<gN, TB>>>();
    scan1_kernel<<<nb, 1024>>>(N_NODES);
    scan2_kernel<<<1, 32>>>(nb);
    scan3_kernel<<<nb, 1024>>>(N_NODES);
    scatter_kernel<<<gE, TB>>>(edges);

    gemm1_kernel<<<gG, TB>>>(feature, W1, b1);
    gemm2_kernel<<<gG, TB>>>(W2, b2);

    for (int d = 1; d < DORD; ++d)
        hop_kernel<<<gRow, TB>>>(d);
    hop_final_kernel<<<gRow, TB>>>(out);
}

// round 9
// speedup vs baseline: 1.1931x; 1.0053x over previous
#include <cuda_runtime.h>
#include <cuda_fp16.h>
#include <math.h>

#define N_NODES 100000
#define E_EDGES 3200000
#define F_IN    500
#define HID     64
#define CCH     64
#define KFREQ   5
#define DORD    10

// ---------------- scratch (static device globals; no allocation) ----------------
__device__ __align__(16) float  g_xh[N_NODES * HID];     // relu(feature@W1+b1)
__device__ __align__(16) float  g_xc[N_NODES * CCH];     // lin2 output fp32 ("x" added at end)
__device__ __align__(16) __half g_xc16[N_NODES * CCH];   // fp16 copy for hop-1 gather
__device__ __align__(16) __half g_h16A[N_NODES * CCH];   // fp16 diffusion ping (odd-d outputs)
__device__ __align__(16) __half g_h16B[N_NODES * CCH];   // fp16 diffusion pong (even-d outputs)
__device__ __align__(16) float  g_hidden[N_NODES * CCH]; // fp32 accumulator
__device__ __align__(16) long long g_colw[E_EDGES];      // packed {w(float hi32), src(lo32)}
__device__ int    g_deg[N_NODES];
__device__ int    g_indeg[N_NODES];
__device__ float  g_dinv[N_NODES];
__device__ int    g_rowptr[N_NODES + 1];
__device__ int    g_cursor[N_NODES + 1];
__device__ int    g_tmp[N_NODES];
__device__ int    g_btot[128];
__device__ int    g_boff[128];
__device__ float  g_coeff[16];

// ---------------- small utility kernels ----------------
__global__ void zero_counts_kernel() {
    int i = blockIdx.x * blockDim.x + threadIdx.x;
    if (i < N_NODES) { g_deg[i] = 0; g_indeg[i] = 0; }
}

// coeff[d] = sum_k alpha[k]*SINC[k][d] + beta[k]*COSC[k][d] (tables in fp64, cast)
__global__ void coeff_kernel(const float* __restrict__ alpha,
                             const float* __restrict__ beta) {
    int d = threadIdx.x;
    if (d > DORD) return;
    float acc = 0.0f;
    for (int k = 0; k < KFREQ; ++k) {
        double x = (double)(k + 1) * 3.14159265358979323846;
        double p = 1.0;
        for (int i = 0; i < d; ++i) p *= x;
        double f = 1.0;
        for (int i = 2; i <= d; ++i) f *= (double)i;
        double sinc = 0.0, cosc = 0.0;
        if ((d & 1) == 0) {
            double sgn = (((d / 2) & 1) == 0) ? 1.0 : -1.0;
            cosc = sgn * p / f;
        } else {
            double sgn = ((((d - 1) / 2) & 1) == 0) ? 1.0 : -1.0;
            sinc = sgn * p / f;
        }
        acc += alpha[k] * (float)sinc + beta[k] * (float)cosc;
    }
    g_coeff[d] = acc;
}

// edges buffer is int32 (jax x64 disabled)
__global__ void pass1_kernel(const int* __restrict__ edges) {
    int e = blockIdx.x * blockDim.x + threadIdx.x;
    if (e >= E_EDGES) return;
    int s = edges[e];
    int d = edges[E_EDGES + e];
    if (s != d && (unsigned)s < N_NODES && (unsigned)d < N_NODES) {
        atomicAdd(&g_deg[s], 1);
        atomicAdd(&g_indeg[d], 1);
    }
}

__global__ void dinv_kernel() {
    int i = blockIdx.x * blockDim.x + threadIdx.x;
    if (i >= N_NODES) return;
    int dg = g_deg[i];
    g_dinv[i] = (dg > 0) ? rsqrtf((float)dg) : 0.0f;
}

// ------- exclusive scan of g_indeg -> g_rowptr -------
__global__ void scan1_kernel(int n) {
    __shared__ int s[1024];
    int i = blockIdx.x * 1024 + threadIdx.x;
    int v = (i < n) ? g_indeg[i] : 0;
    s[threadIdx.x] = v;
    __syncthreads();
    for (int off = 1; off < 1024; off <<= 1) {
        int t = (threadIdx.x >= off) ? s[threadIdx.x - off] : 0;
        __syncthreads();
        s[threadIdx.x] += t;
        __syncthreads();
    }
    if (i < n) g_tmp[i] = s[threadIdx.x];
    if (threadIdx.x == 1023) g_btot[blockIdx.x] = s[1023];
}

__global__ void scan2_kernel(int nb) {
    if (threadIdx.x == 0 && blockIdx.x == 0) {
        int run = 0;
        for (int b = 0; b < nb; ++b) { g_boff[b] = run; run += g_btot[b]; }
    }
}

__global__ void scan3_kernel(int n) {
    int i = blockIdx.x * 1024 + threadIdx.x;
    if (i < n) {
        int v = g_tmp[i] + g_boff[blockIdx.x];
        g_rowptr[i + 1] = v;
        if (i + 1 < N_NODES) g_cursor[i + 1] = v;
        if (i == 0) { g_rowptr[0] = 0; g_cursor[0] = 0; }
    }
}

__global__ void scatter_kernel(const int* __restrict__ edges) {
    int e = blockIdx.x * blockDim.x + threadIdx.x;
    if (e >= E_EDGES) return;
    int s = edges[e];
    int d = edges[E_EDGES + e];
    if (s != d && (unsigned)s < N_NODES && (unsigned)d < N_NODES) {
        float w = -(g_dinv[s] * g_dinv[d]);
        int pos = atomicAdd(&g_cursor[d], 1);
        g_colw[pos] = ((long long)(unsigned long long)__float_as_uint(w) << 32)
                      | (unsigned long long)(unsigned)s;
    }
}

// ---------------- packed f32x2 FMA helper ----------------
__device__ __forceinline__ void ffma2(unsigned long long& acc,
                                      unsigned long long a,
                                      unsigned long long b) {
    asm("fma.rn.f32x2 %0, %1, %2, %0;" : "+l"(acc) : "l"(a), "l"(b));
}
__device__ __forceinline__ float2 unpack2(unsigned long long p) {
    float2 r;
    asm("mov.b64 {%0, %1}, %2;" : "=f"(r.x), "=f"(r.y) : "l"(p));
    return r;
}

// ---------------- GEMM1: xh = relu(feature @ W1 + b1) ----------------
__global__ __launch_bounds__(256) void gemm1_kernel(const float* __restrict__ feat,
                                                    const float* __restrict__ W1,
                                                    const float* __restrict__ b1) {
    __shared__ __align__(16) float2 As2[16 * 65];
    __shared__ __align__(16) float  Ws[16 * 64];
    int tid = threadIdx.x;
    int tx = tid & 15, ty = tid >> 4;
    int row0 = blockIdx.x * 64;
    int kkA = tid & 15;
    int rA = (tid >> 4) * 4;
    unsigned long long acc[4][2] = {};

    for (int k0 = 0; k0 < F_IN; k0 += 16) {
        bool kok = (k0 + kkA) < F_IN;
#pragma unroll
        for (int i = 0; i < 4; ++i) {
            int r = row0 + rA + i;
            float v = 0.0f;
            if (r < N_NODES && kok) v = __ldcs(&feat[r * F_IN + k0 + kkA]);
            As2[kkA * 65 + rA + i] = make_float2(v, v);
        }
        {
            int L = tid * 4;
            int kk = L >> 6;
            int n = L & 63;
            float4 w4 = make_float4(0.f, 0.f, 0.f, 0.f);
            if (k0 + kk < F_IN) w4 = *(const float4*)&W1[(k0 + kk) * HID + n];
            *(float4*)&Ws[kk * 64 + n] = w4;
        }
        __syncthreads();
#pragma unroll
        for (int kk = 0; kk < 16; ++kk) {
            ulonglong2 bp = *(const ulonglong2*)&Ws[kk * 64 + tx * 4];
            const unsigned long long* ap =
                (const unsigned long long*)&As2[kk * 65 + ty * 4];
#pragma unroll
            for (int i = 0; i < 4; ++i) {
                unsigned long long a = ap[i];
                ffma2(acc[i][0], a, bp.x);
                ffma2(acc[i][1], a, bp.y);
            }
        }
        __syncthreads();
    }
#pragma unroll
    for (int i = 0; i < 4; ++i) {
        int r = row0 + ty * 4 + i;
        if (r >= N_NODES) continue;
        float2 p0 = unpack2(acc[i][0]);
        float2 p1 = unpack2(acc[i][1]);
        int c = tx * 4;
        g_xh[r * HID + c + 0] = fmaxf(p0.x + __ldg(&b1[c + 0]), 0.0f);
        g_xh[r * HID + c + 1] = fmaxf(p0.y + __ldg(&b1[c + 1]), 0.0f);
        g_xh[r * HID + c + 2] = fmaxf(p1.x + __ldg(&b1[c + 2]), 0.0f);
        g_xh[r * HID + c + 3] = fmaxf(p1.y + __ldg(&b1[c + 3]), 0.0f);
    }
}

// ---------------- GEMM2: xc = xh @ W2 + b2 ; hidden = c0*xc ; xc16 = fp16(xc) ----------------
__global__ __launch_bounds__(256) void gemm2_kernel(const float* __restrict__ W2,
                                                    const float* __restrict__ b2) {
    __shared__ __align__(16) float2 As2[16 * 65];
    __shared__ __align__(16) float  Ws[16 * 64];
    int tid = threadIdx.x;
    int tx = tid & 15, ty = tid >> 4;
    int row0 = blockIdx.x * 64;
    int kkA = tid & 15;
    int rA = (tid >> 4) * 4;
    unsigned long long acc[4][2] = {};

    for (int k0 = 0; k0 < HID; k0 += 16) {
#pragma unroll
        for (int i = 0; i < 4; ++i) {
            int r = row0 + rA + i;
            float v = 0.0f;
            if (r < N_NODES) v = g_xh[r * HID + k0 + kkA];
            As2[kkA * 65 + rA + i] = make_float2(v, v);
        }
        {
            int L = tid * 4;
            int kk = L >> 6;
            int n = L & 63;
            float4 w4 = *(const float4*)&W2[(k0 + kk) * CCH + n];
            *(float4*)&Ws[kk * 64 + n] = w4;
        }
        __syncthreads();
#pragma unroll
        for (int kk = 0; kk < 16; ++kk) {
            ulonglong2 bp = *(const ulonglong2*)&Ws[kk * 64 + tx * 4];
            const unsigned long long* ap =
                (const unsigned long long*)&As2[kk * 65 + ty * 4];
#pragma unroll
            for (int i = 0; i < 4; ++i) {
                unsigned long long a = ap[i];
                ffma2(acc[i][0], a, bp.x);
                ffma2(acc[i][1], a, bp.y);
            }
        }
        __syncthreads();
    }
    float c0 = g_coeff[0];
#pragma unroll
    for (int i = 0; i < 4; ++i) {
        int r = row0 + ty * 4 + i;
        if (r >= N_NODES) continue;
        float2 p0 = unpack2(acc[i][0]);
        float2 p1 = unpack2(acc[i][1]);
        int c = tx * 4;
        float v0 = p0.x + __ldg(&b2[c + 0]);
        float v1 = p0.y + __ldg(&b2[c + 1]);
        float v2 = p1.x + __ldg(&b2[c + 2]);
        float v3 = p1.y + __ldg(&b2[c + 3]);
        float* xr = &g_xc[r * CCH + c];
        xr[0] = v0; xr[1] = v1; xr[2] = v2; xr[3] = v3;
        float* hr = &g_hidden[r * CCH + c];
        hr[0] = c0 * v0; hr[1] = c0 * v1; hr[2] = c0 * v2; hr[3] = c0 * v3;
        __half2* x16 = (__half2*)&g_xc16[r * CCH + c];
        x16[0] = __floats2half2_rn(v0, v1);
        x16[1] = __floats2half2_rn(v2, v3);
    }
}

// ---------------- diffusion hop (shfl-staged gathers, fp16 state, fp32 accumulate) ----------------
// One warp per dst row. Warp loads 32 edge records at once (coalesced), broadcasts
// (src,w) via SHFL, then issues 32 independent row-gathers.
__device__ __forceinline__ float2 hop_row_accum(const __half2* __restrict__ tin,
                                                int beg, int end, int lane) {
    float2 acc = make_float2(0.f, 0.f);
    const __half2* tlane = tin + lane;
    int j0 = beg;
    // full 32-edge chunks
    for (; j0 + 32 <= end; j0 += 32) {
        long long m = __ldg(&g_colw[j0 + lane]);
        int      ms = (int)(m & 0xFFFFFFFFLL);
        unsigned mw = (unsigned)(((unsigned long long)m) >> 32);
#pragma unroll
        for (int t = 0; t < 32; ++t) {
            int   s = __shfl_sync(0xFFFFFFFFu, ms, t);
            float w = __uint_as_float(__shfl_sync(0xFFFFFFFFu, mw, t));
            float2 v = __half22float2(__ldg(&tlane[s * 32]));
            acc.x = fmaf(w, v.x, acc.x);
            acc.y = fmaf(w, v.y, acc.y);
        }
    }
    // tail
    int n = end - j0;
    if (n > 0) {
        long long m = (lane < n) ? __ldg(&g_colw[j0 + lane]) : 0LL;
        int      ms = (int)(m & 0xFFFFFFFFLL);
        unsigned mw = (unsigned)(((unsigned long long)m) >> 32);
#pragma unroll 8
        for (int t = 0; t < n; ++t) {
            int   s = __shfl_sync(0xFFFFFFFFu, ms, t);
            float w = __uint_as_float(__shfl_sync(0xFFFFFFFFu, mw, t));
            float2 v = __half22float2(__ldg(&tlane[s * 32]));
            acc.x = fmaf(w, v.x, acc.x);
            acc.y = fmaf(w, v.y, acc.y);
        }
    }
    return acc;
}

// ping-pong: d odd -> writes A, d even -> writes B. Input = (d-1)'s output.
// hidden is single-use per hop -> evict-first (__ldcs/__stcs) so L2 keeps
// tin/tout/colw resident and gathers stay L2-hits.
__global__ __launch_bounds__(256) void hop_kernel(int d) {
    int row = blockIdx.x * 8 + (threadIdx.x >> 5);
    if (row >= N_NODES) return;
    int lane = threadIdx.x & 31;

    const __half2* tin = (d == 1) ? (const __half2*)g_xc16
                        : ((d & 1) ? (const __half2*)g_h16B : (const __half2*)g_h16A);
    __half2* tout = (d & 1) ? (__half2*)g_h16A : (__half2*)g_h16B;

    int beg = __ldg(&g_rowptr[row]);
    int end = __ldg(&g_rowptr[row + 1]);
    float2 acc = hop_row_accum(tin, beg, end, lane);

    int idx = row * 32 + lane;
    tout[idx] = __floats2half2_rn(acc.x, acc.y);
    float c = g_coeff[d];
    float2 h = __ldcs(&((float2*)g_hidden)[idx]);
    h.x = fmaf(c, acc.x, h.x);
    h.y = fmaf(c, acc.y, h.y);
    __stcs(&((float2*)g_hidden)[idx], h);
}

// ---------------- last hop (d=10) fused with log_softmax epilogue ----------------
// d=9 is odd -> its output lives in g_h16A.
__global__ __launch_bounds__(256) void hop_final_kernel(float* __restrict__ out) {
    int row = blockIdx.x * 8 + (threadIdx.x >> 5);
    if (row >= N_NODES) return;
    int lane = threadIdx.x & 31;

    const __half2* tin = (const __half2*)g_h16A;

    int beg = __ldg(&g_rowptr[row]);
    int end = __ldg(&g_rowptr[row + 1]);
    float2 acc = hop_row_accum(tin, beg, end, lane);

    int idx = row * 32 + lane;
    float c = g_coeff[DORD];
    float2 h = __ldcs(&((const float2*)g_hidden)[idx]);
    float2 x = __ldcs(&((const float2*)g_xc)[idx]);
    float2 v;
    v.x = fmaf(c, acc.x, h.x) + x.x;
    v.y = fmaf(c, acc.y, h.y) + x.y;
    float m = fmaxf(v.x, v.y);
#pragma unroll
    for (int o = 16; o; o >>= 1) m = fmaxf(m, __shfl_xor_sync(0xFFFFFFFFu, m, o));
    float s = expf(v.x - m) + expf(v.y - m);
#pragma unroll
    for (int o = 16; o; o >>= 1) s += __shfl_xor_sync(0xFFFFFFFFu, s, o);
    float l = m + logf(s);
    __stcs(&((float2*)out)[idx], make_float2(v.x - l, v.y - l));
}

// ---------------- launch ----------------
extern "C" void kernel_launch(void* const* d_in, const int* in_sizes, int n_in,
                              void* d_out, int out_size) {
    const float* feature = (const float*)d_in[0];
    const int*   edges   = (const int*)d_in[1];   // int32
    const float* W1      = (const float*)d_in[2];
    const float* b1      = (const float*)d_in[3];
    const float* W2      = (const float*)d_in[4];
    const float* b2      = (const float*)d_in[5];
    const float* alpha   = (const float*)d_in[6];
    const float* beta    = (const float*)d_in[7];
    float* out           = (float*)d_out;

    const int TB = 256;
    int gN   = (N_NODES + TB - 1) / TB;
    int gE   = (E_EDGES + TB - 1) / TB;
    int gRow = (N_NODES + 7) / 8;
    int gG   = (N_NODES + 63) / 64;
    int nb   = (N_NODES + 1023) / 1024;

    zero_counts_kernel<<<gN, TB>>>();
    coeff_kernel<<<1, 32>>>(alpha, beta);
    pass1_kernel<<<gE, TB>>>(edges);
    dinv_kernel<<<gN, TB>>>();
    scan1_kernel<<<nb, 1024>>>(N_NODES);
    scan2_kernel<<<1, 32>>>(nb);
    scan3_kernel<<<nb, 1024>>>(N_NODES);
    scatter_kernel<<<gE, TB>>>(edges);

    gemm1_kernel<<<gG, TB>>>(feature, W1, b1);
    gemm2_kernel<<<gG, TB>>>(W2, b2);

    for (int d = 1; d < DORD; ++d)
        hop_kernel<<<gRow, TB>>>(d);
    hop_final_kernel<<<gRow, TB>>>(out);
}